// round 14
// baseline (speedup 1.0000x reference)
#include <cuda_runtime.h>

// ---------------------------------------------------------------------------
// GraphConstruction: A[i,j] = all_k( ||patch_i[:,k]-patch_j[:,k]||_2 <= 7 )
// score_k(i,j) = sum_{r<16} P[i,r,k]*P[j,r,k] + 1*c_j + c_i*1,  c = 12.25-sq/2
// A[i,j] = no k has score_k < 0 (OR of sign bits == 0).
// R13: R9 gram + (a) two-half compute to cut live acc regs 64->32,
// (b) dynamic smem with opt-in + 100% carveout, (c) launch_bounds(64,10)
// targeting 20 warps/SM. FFMA2 chains bit-identical to R2-R12.
// ---------------------------------------------------------------------------

#define NP 4096
#define RAUG 18
#define GRAM_SMEM_BYTES (2 * 2 * RAUG * 64 * 4)   // sA + sB double buffers

static __device__ float g_P[16 * RAUG * NP];   // [k][r][n], 4.5 MB

// ---------------- helpers ---------------------------------------------------
__device__ __forceinline__ unsigned long long bcast2(float x) {
    unsigned long long r;
    asm("mov.b64 %0, {%1, %1};" : "=l"(r) : "f"(x));
    return r;
}
__device__ __forceinline__ void ffma2(unsigned long long& d,
                                      unsigned long long a,
                                      unsigned long long b) {
    asm("fma.rn.f32x2 %0, %1, %2, %3;" : "=l"(d) : "l"(a), "l"(b), "l"(d));
}
__device__ __forceinline__ void split2(unsigned& lo, unsigned& hi,
                                       unsigned long long v) {
    asm("mov.b64 {%0, %1}, %2;" : "=r"(lo), "=r"(hi) : "l"(v));
}
__device__ __forceinline__ unsigned prmt(unsigned a, unsigned b, unsigned sel) {
    unsigned d;
    asm("prmt.b32 %0, %1, %2, %3;" : "=r"(d) : "r"(a), "r"(b), "r"(sel));
    return d;
}
__device__ __forceinline__ void cp_async16(void* smem, const void* gmem) {
    unsigned s = (unsigned)__cvta_generic_to_shared(smem);
    asm volatile("cp.async.cg.shared.global [%0], [%1], 16;" :: "r"(s), "l"(gmem));
}
#define CP_COMMIT() asm volatile("cp.async.commit_group;")
#define CP_WAIT0()  asm volatile("cp.async.wait_group 0;")

// ---------------- fused prep: gather + augmentation (R9, unchanged) ---------
__global__ void __launch_bounds__(256) prep_kernel(const float* __restrict__ x) {
    const int k = blockIdx.x >> 4;
    const int q = blockIdx.x & 15;
    const int t = threadIdx.x;                 // 256 threads
    const int n = q * 256 + t;
    const int c = n & 15;
    const int j = (n >> 4) & 15;
    const int m = n >> 8;

    float v[16];
#pragma unroll
    for (int r = 0; r < 16; r++) {
        int h = (c << 6) + ((r >> 2) << 4) + m;
        int w = ((16 * (r & 3) + k) << 4) + j;
        v[r] = x[h * 1024 + w];
    }
#pragma unroll
    for (int r = 0; r < 16; r++)
        g_P[(k * RAUG + r) * NP + n] = v[r];

    float s = 0.0f;
#pragma unroll
    for (int r = 0; r < 16; r++)
        s = fmaf(v[r], v[r], s);               // identical chain to before

    g_P[(k * RAUG + 16) * NP + n] = 1.0f;
    g_P[(k * RAUG + 17) * NP + n] = 12.25f - 0.5f * s;
}

// ---------------- main: tiled pair kernel ------------------------------------
// Tile 64 i x 64 j, 64 threads, 8x8 per thread (j packed as f32x2).
// Compute split into two i-halves of 4 rows to halve live accumulators.
__global__ void __launch_bounds__(64, 10) gram_kernel(float* __restrict__ A) {
    extern __shared__ __align__(16) float dyn[];
    float* sAd = dyn;                         // [2][RAUG][64]
    float* sBd = dyn + 2 * RAUG * 64;         // [2][RAUG][64]

    const int bid = blockIdx.x;
    int jb = (int)((sqrtf(8.0f * (float)bid + 1.0f) - 1.0f) * 0.5f);
    while ((jb * (jb + 1)) / 2 > bid) jb--;
    while (((jb + 1) * (jb + 2)) / 2 <= bid) jb++;
    const int ib = bid - (jb * (jb + 1)) / 2;   // 0..jb
    const int i0 = ib * 64;
    const int j0 = jb * 64;

    const int tid = threadIdx.x;
    const int tx = tid & 7;              // j group: j = {tx*4..+3} U {32+tx*4..+3}
    const int ty = tid >> 3;             // i group 0..7

    auto issue = [&](int buf, int k) {
        for (int idx = tid; idx < 288; idx += 64) {      // sA: 18 x 16 float4
            int r = idx >> 4, c = idx & 15;
            cp_async16(&sAd[(buf * RAUG + r) * 64 + c * 4],
                       &g_P[(k * RAUG + r) * NP + i0 + c * 4]);
        }
        for (int idx = tid; idx < 288; idx += 64) {      // sB: rows 16/17 swapped
            int r = idx >> 4, c = idx & 15;
            int rs = (r < 16) ? r : (33 - r);
            cp_async16(&sBd[(buf * RAUG + r) * 64 + c * 4],
                       &g_P[(k * RAUG + rs) * NP + j0 + c * 4]);
        }
    };

    unsigned msk[8][2];
#pragma unroll
    for (int a = 0; a < 8; a++) { msk[a][0] = 0u; msk[a][1] = 0u; }

    issue(0, 0);
    CP_COMMIT();

#pragma unroll 1
    for (int k = 0; k < 16; k++) {
        const int buf = k & 1;
        CP_WAIT0();
        __syncthreads();          // buf staged AND everyone done with buf^1
        if (k < 15) {
            issue(buf ^ 1, k + 1);
            CP_COMMIT();
        }

        const float* pA = &sAd[buf * RAUG * 64 + ty * 8];
        const float* pB = &sBd[buf * RAUG * 64 + tx * 4];

#pragma unroll 1
        for (int h = 0; h < 2; h++) {         // two i-halves: acc 32 regs live
            unsigned long long acc[4][4];
#pragma unroll
            for (int a = 0; a < 4; a++)
#pragma unroll
                for (int b = 0; b < 4; b++) acc[a][b] = 0ULL;

#pragma unroll
            for (int r = 0; r < RAUG; r++) {
                float4 a0 = *(const float4*)(pA + r * 64 + h * 4);
                ulonglong2 b0 = *(const ulonglong2*)(pB + r * 64);
                ulonglong2 b1 = *(const ulonglong2*)(pB + r * 64 + 32);
                unsigned long long bb[4] = {b0.x, b0.y, b1.x, b1.y};
                float av[4] = {a0.x, a0.y, a0.z, a0.w};
#pragma unroll
                for (int ii = 0; ii < 4; ii++) {
                    unsigned long long aa = bcast2(av[ii]);
#pragma unroll
                    for (int jj = 0; jj < 4; jj++) ffma2(acc[ii][jj], aa, bb[jj]);
                }
            }

            // fold sign bits into msk[h*4+ii][p]
#pragma unroll
            for (int ii = 0; ii < 4; ii++)
#pragma unroll
                for (int p = 0; p < 2; p++) {
                    unsigned lo0, hi0, lo1, hi1;
                    split2(lo0, hi0, acc[ii][2 * p]);
                    split2(lo1, hi1, acc[ii][2 * p + 1]);
                    unsigned t0 = prmt(lo0, hi0, 0xFBFBu);
                    unsigned t1 = prmt(lo1, hi1, 0xFBFBu);
                    msk[h * 4 + ii][p] |= prmt(t0, t1, 0x5410u);
                }
        }
    }

    // ---- epilogue: sign byte==0 -> 1.0f ----
    // direct: A[i, j]
#pragma unroll
    for (int ii = 0; ii < 8; ii++)
#pragma unroll
        for (int p = 0; p < 2; p++) {
            unsigned m = msk[ii][p];
            float4 o;
            o.x = (m & 0x00000080u) ? 0.0f : 1.0f;
            o.y = (m & 0x00008000u) ? 0.0f : 1.0f;
            o.z = (m & 0x00800000u) ? 0.0f : 1.0f;
            o.w = (m & 0x80000000u) ? 0.0f : 1.0f;
            size_t off = (size_t)(i0 + ty * 8 + ii) * 4096 + j0 + p * 32 + tx * 4;
            *(float4*)&A[off] = o;
        }
    // transposed: A[j, i]; skip rows inside this tile's i-range (diag tiles)
#pragma unroll
    for (int p = 0; p < 2; p++)
#pragma unroll
        for (int c = 0; c < 4; c++) {
            int rowj = j0 + p * 32 + tx * 4 + c;
            if (rowj >= i0 && rowj < i0 + 64) continue;   // diag: direct covers
            unsigned bit = 0x80u << (8 * c);
            float4 o0, o1;
            o0.x = (msk[0][p] & bit) ? 0.0f : 1.0f;
            o0.y = (msk[1][p] & bit) ? 0.0f : 1.0f;
            o0.z = (msk[2][p] & bit) ? 0.0f : 1.0f;
            o0.w = (msk[3][p] & bit) ? 0.0f : 1.0f;
            o1.x = (msk[4][p] & bit) ? 0.0f : 1.0f;
            o1.y = (msk[5][p] & bit) ? 0.0f : 1.0f;
            o1.z = (msk[6][p] & bit) ? 0.0f : 1.0f;
            o1.w = (msk[7][p] & bit) ? 0.0f : 1.0f;
            size_t off = (size_t)rowj * 4096 + i0 + ty * 8;
            *(float4*)&A[off]     = o0;
            *(float4*)&A[off + 4] = o1;
        }
}

// ---------------------------------------------------------------------------
extern "C" void kernel_launch(void* const* d_in, const int* in_sizes, int n_in,
                              void* d_out, int out_size) {
    const float* x = (const float*)d_in[0];
    float* A = (float*)d_out;

    // Host-side attribute sets (idempotent, not stream ops — capture safe):
    cudaFuncSetAttribute(gram_kernel,
                         cudaFuncAttributeMaxDynamicSharedMemorySize,
                         GRAM_SMEM_BYTES);
    cudaFuncSetAttribute(gram_kernel,
                         cudaFuncAttributePreferredSharedMemoryCarveout, 100);

    prep_kernel<<<256, 256>>>(x);                      // fused gather + aug
    gram_kernel<<<2080, 64, GRAM_SMEM_BYTES>>>(A);     // 64x64 triangle tiles
}

// round 15
// speedup vs baseline: 4.4833x; 4.4833x over previous
#include <cuda_runtime.h>

// ---------------------------------------------------------------------------
// GraphConstruction: A[i,j] = all_k( ||patch_i[:,k]-patch_j[:,k]||_2 <= 7 )
// score_k(i,j) = sum_{r<16} P[i,r,k]*P[j,r,k] + 1*c_j + c_i*1,  c = 12.25-sq/2
// A[i,j] = no k has score_k < 0 (OR of sign bits == 0).
// FINAL (== R9, best measured 98.78us): fused prep + static-smem 64x64 gram.
// FFMA2 chain order/operands bit-stable across all rounds (rel_err 9.378e-4).
// ---------------------------------------------------------------------------

#define NP 4096
#define RAUG 18

static __device__ float g_P[16 * RAUG * NP];   // [k][r][n], 4.5 MB

// ---------------- helpers ---------------------------------------------------
__device__ __forceinline__ unsigned long long bcast2(float x) {
    unsigned long long r;
    asm("mov.b64 %0, {%1, %1};" : "=l"(r) : "f"(x));
    return r;
}
__device__ __forceinline__ void ffma2(unsigned long long& d,
                                      unsigned long long a,
                                      unsigned long long b) {
    asm("fma.rn.f32x2 %0, %1, %2, %3;" : "=l"(d) : "l"(a), "l"(b), "l"(d));
}
__device__ __forceinline__ void split2(unsigned& lo, unsigned& hi,
                                       unsigned long long v) {
    asm("mov.b64 {%0, %1}, %2;" : "=r"(lo), "=r"(hi) : "l"(v));
}
__device__ __forceinline__ unsigned prmt(unsigned a, unsigned b, unsigned sel) {
    unsigned d;
    asm("prmt.b32 %0, %1, %2, %3;" : "=r"(d) : "r"(a), "r"(b), "r"(sel));
    return d;
}
__device__ __forceinline__ void cp_async16(void* smem, const void* gmem) {
    unsigned s = (unsigned)__cvta_generic_to_shared(smem);
    asm volatile("cp.async.cg.shared.global [%0], [%1], 16;" :: "r"(s), "l"(gmem));
}
#define CP_COMMIT() asm volatile("cp.async.commit_group;")
#define CP_WAIT0()  asm volatile("cp.async.wait_group 0;")

// ---------------- fused prep: gather + augmentation --------------------------
// Block = (k, quarter q). Thread owns one n: loads all 16 r values (MLP=16),
// writes rows 0..15 (coalesced across lanes), computes sq from registers via
// the ascending-r fmaf chain (bit-identical), writes rows 16/17.
__global__ void __launch_bounds__(256) prep_kernel(const float* __restrict__ x) {
    const int k = blockIdx.x >> 4;
    const int q = blockIdx.x & 15;
    const int t = threadIdx.x;                 // 256 threads
    const int n = q * 256 + t;
    const int c = n & 15;
    const int j = (n >> 4) & 15;
    const int m = n >> 8;

    float v[16];
#pragma unroll
    for (int r = 0; r < 16; r++) {
        int h = (c << 6) + ((r >> 2) << 4) + m;
        int w = ((16 * (r & 3) + k) << 4) + j;
        v[r] = x[h * 1024 + w];
    }
#pragma unroll
    for (int r = 0; r < 16; r++)
        g_P[(k * RAUG + r) * NP + n] = v[r];

    float s = 0.0f;
#pragma unroll
    for (int r = 0; r < 16; r++)
        s = fmaf(v[r], v[r], s);               // identical chain to before

    g_P[(k * RAUG + 16) * NP + n] = 1.0f;
    g_P[(k * RAUG + 17) * NP + n] = 12.25f - 0.5f * s;
}

// ---------------- main: tiled pair kernel -----------------------------------
// Tile 64 i x 64 j, 64 threads, 8x8 per thread (j packed as f32x2).
// Static smem double buffers fed by cp.async; one __syncthreads per k.
__global__ void __launch_bounds__(64, 8) gram_kernel(float* __restrict__ A) {
    const int bid = blockIdx.x;
    int jb = (int)((sqrtf(8.0f * (float)bid + 1.0f) - 1.0f) * 0.5f);
    while ((jb * (jb + 1)) / 2 > bid) jb--;
    while (((jb + 1) * (jb + 2)) / 2 <= bid) jb++;
    const int ib = bid - (jb * (jb + 1)) / 2;   // 0..jb
    const int i0 = ib * 64;
    const int j0 = jb * 64;

    __shared__ __align__(16) float sA[2][RAUG][64];
    __shared__ __align__(16) float sB[2][RAUG][64];

    const int tid = threadIdx.x;
    const int tx = tid & 7;              // j group: j = {tx*4..+3} U {32+tx*4..+3}
    const int ty = tid >> 3;             // i group 0..7

    auto issue = [&](int buf, int k) {
        for (int idx = tid; idx < 288; idx += 64) {      // sA: 18 x 16 float4
            int r = idx >> 4, c = idx & 15;
            cp_async16(&sA[buf][r][c * 4], &g_P[(k * RAUG + r) * NP + i0 + c * 4]);
        }
        for (int idx = tid; idx < 288; idx += 64) {      // sB: rows 16/17 swapped
            int r = idx >> 4, c = idx & 15;
            int rs = (r < 16) ? r : (33 - r);
            cp_async16(&sB[buf][r][c * 4], &g_P[(k * RAUG + rs) * NP + j0 + c * 4]);
        }
    };

    unsigned msk[8][2];
#pragma unroll
    for (int a = 0; a < 8; a++) { msk[a][0] = 0u; msk[a][1] = 0u; }

    issue(0, 0);
    CP_COMMIT();

#pragma unroll 1
    for (int k = 0; k < 16; k++) {
        const int buf = k & 1;
        CP_WAIT0();
        __syncthreads();          // buf staged AND everyone done with buf^1
        if (k < 15) {
            issue(buf ^ 1, k + 1);
            CP_COMMIT();
        }

        unsigned long long acc[8][4];
#pragma unroll
        for (int a = 0; a < 8; a++)
#pragma unroll
            for (int b = 0; b < 4; b++) acc[a][b] = 0ULL;

#pragma unroll
        for (int r = 0; r < RAUG; r++) {
            float4 a0 = *(const float4*)&sA[buf][r][ty * 8];
            float4 a1 = *(const float4*)&sA[buf][r][ty * 8 + 4];
            ulonglong2 b0 = *(const ulonglong2*)&sB[buf][r][tx * 4];
            ulonglong2 b1 = *(const ulonglong2*)&sB[buf][r][32 + tx * 4];
            unsigned long long bb[4] = {b0.x, b0.y, b1.x, b1.y};
            float av[8] = {a0.x, a0.y, a0.z, a0.w, a1.x, a1.y, a1.z, a1.w};
#pragma unroll
            for (int ii = 0; ii < 8; ii++) {
                unsigned long long aa = bcast2(av[ii]);
#pragma unroll
                for (int jj = 0; jj < 4; jj++) ffma2(acc[ii][jj], aa, bb[jj]);
            }
        }

        // fold sign bits: msk[ii][p] bytes = signs of j = p*32 + tx*4 + {0..3}
#pragma unroll
        for (int ii = 0; ii < 8; ii++)
#pragma unroll
            for (int p = 0; p < 2; p++) {
                unsigned lo0, hi0, lo1, hi1;
                split2(lo0, hi0, acc[ii][2 * p]);
                split2(lo1, hi1, acc[ii][2 * p + 1]);
                unsigned t0 = prmt(lo0, hi0, 0xFBFBu);
                unsigned t1 = prmt(lo1, hi1, 0xFBFBu);
                msk[ii][p] |= prmt(t0, t1, 0x5410u);
            }
    }

    // ---- epilogue: sign byte==0 -> 1.0f ----
    // direct: A[i, j]
#pragma unroll
    for (int ii = 0; ii < 8; ii++)
#pragma unroll
        for (int p = 0; p < 2; p++) {
            unsigned m = msk[ii][p];
            float4 o;
            o.x = (m & 0x00000080u) ? 0.0f : 1.0f;
            o.y = (m & 0x00008000u) ? 0.0f : 1.0f;
            o.z = (m & 0x00800000u) ? 0.0f : 1.0f;
            o.w = (m & 0x80000000u) ? 0.0f : 1.0f;
            size_t off = (size_t)(i0 + ty * 8 + ii) * 4096 + j0 + p * 32 + tx * 4;
            *(float4*)&A[off] = o;
        }
    // transposed: A[j, i]; skip rows inside this tile's i-range (diag tiles)
#pragma unroll
    for (int p = 0; p < 2; p++)
#pragma unroll
        for (int c = 0; c < 4; c++) {
            int rowj = j0 + p * 32 + tx * 4 + c;
            if (rowj >= i0 && rowj < i0 + 64) continue;   // diag: direct covers
            unsigned bit = 0x80u << (8 * c);
            float4 o0, o1;
            o0.x = (msk[0][p] & bit) ? 0.0f : 1.0f;
            o0.y = (msk[1][p] & bit) ? 0.0f : 1.0f;
            o0.z = (msk[2][p] & bit) ? 0.0f : 1.0f;
            o0.w = (msk[3][p] & bit) ? 0.0f : 1.0f;
            o1.x = (msk[4][p] & bit) ? 0.0f : 1.0f;
            o1.y = (msk[5][p] & bit) ? 0.0f : 1.0f;
            o1.z = (msk[6][p] & bit) ? 0.0f : 1.0f;
            o1.w = (msk[7][p] & bit) ? 0.0f : 1.0f;
            size_t off = (size_t)rowj * 4096 + i0 + ty * 8;
            *(float4*)&A[off]     = o0;
            *(float4*)&A[off + 4] = o1;
        }
}

// ---------------------------------------------------------------------------
extern "C" void kernel_launch(void* const* d_in, const int* in_sizes, int n_in,
                              void* d_out, int out_size) {
    const float* x = (const float*)d_in[0];
    float* A = (float*)d_out;

    prep_kernel<<<256, 256>>>(x);          // fused gather + augmentation
    gram_kernel<<<2080, 64>>>(A);          // 64x64 triangle tiles
}